// round 10
// baseline (speedup 1.0000x reference)
#include <cuda_runtime.h>
#include <cuda_bf16.h>
#include <cstdint>

#define N_NODES 50000
#define NPAD    50048             // 391*128
#define EMB     128
#define R_REL   9
#define S_REL   18
#define NW      19
#define N_EDGES 800000
#define E2      (2*N_EDGES)
#define NSEG    (S_REL*N_NODES)   // 900000
#define KTOT    2560              // 19*128 + 128 (bias block padded to 128)
#define KW      640               // KTOT/4 packed words per row
#define KW4     160               // KTOT/16 uint4 per row
#define NCH     20                // K chunks of 128
#define TILES_M 391

// smem: 4 int8 arrays (Ahi,Alo,Bhi,Blo) x 2 stages; 128 rows x 128 s8, stride 144
#define SROW2   144
#define ATILE2  18432             // 128*144
#define STAGE_SZ (4*ATILE2)       // 73728
#define OFF_AHI 0
#define OFF_ALO ATILE2
#define OFF_BHI (2*ATILE2)
#define OFF_BLO (3*ATILE2)
#define GEMM_DSM (2*STAGE_SZ)     // 147456

#define S1 6.103515625e-5f        // 2^-14
#define S2 4.76837158203125e-7f   // 2^-21

// -------- scratch (device globals) --------
__device__ int   g_cnt2[NSEG];
__device__ float g_alpha2[NSEG];
__device__ float g_gamma2[NSEG];
__device__ float g_A[N_NODES];
__device__ int   g_ndeg[N_NODES];
__device__ int   g_noff[N_NODES + 1];
__device__ int   g_soff[NSEG + 1];
__device__ int   g_cur2[NSEG];
__device__ int   g_bsum[64];
__device__ int   g_boff[64];
__device__ int   g_rec[E2];
__device__ float g_H[(size_t)N_NODES * EMB];
__device__ unsigned int g_Qhi[(size_t)NPAD * KW];    // ~128 MB
__device__ unsigned int g_Qlo[(size_t)NPAD * KW];    // ~128 MB
__device__ unsigned int g_Pbhi[2 * EMB * KW];
__device__ unsigned int g_Pblo[2 * EMB * KW];
__device__ float g_sa[N_NODES];
__device__ float g_sb[2 * EMB];

// ------------------------- PTX helpers -------------------------
__device__ __forceinline__ uint32_t smem_u32(const void* p) {
    uint32_t a;
    asm("{ .reg .u64 t; cvta.to.shared.u64 t, %1; cvt.u32.u64 %0, t; }" : "=r"(a) : "l"(p));
    return a;
}
__device__ __forceinline__ void cp_async16(uint32_t dst, const void* src) {
    asm volatile("cp.async.cg.shared.global [%0], [%1], 16;"
                 :: "r"(dst), "l"(src) : "memory");
}
#define CP_COMMIT() asm volatile("cp.async.commit_group;" ::: "memory")
#define CP_WAIT1()  asm volatile("cp.async.wait_group 1;" ::: "memory")
#define CP_WAIT0()  asm volatile("cp.async.wait_group 0;" ::: "memory")

__device__ __forceinline__ void ldsm_x4(uint32_t* r, uint32_t addr) {
    asm volatile("ldmatrix.sync.aligned.m8n8.x4.shared.b16 {%0,%1,%2,%3}, [%4];"
                 : "=r"(r[0]), "=r"(r[1]), "=r"(r[2]), "=r"(r[3]) : "r"(addr));
}
__device__ __forceinline__ void mma_s8(int* c, const uint32_t* a, const uint32_t* b) {
    asm volatile("mma.sync.aligned.m16n8k32.row.col.s32.s8.s8.s32 "
                 "{%0,%1,%2,%3}, {%4,%5,%6,%7}, {%8,%9}, {%0,%1,%2,%3};"
                 : "+r"(c[0]), "+r"(c[1]), "+r"(c[2]), "+r"(c[3])
                 : "r"(a[0]), "r"(a[1]), "r"(a[2]), "r"(a[3]), "r"(b[0]), "r"(b[1]));
}

__device__ __forceinline__ void quant2(float v, float inv_sa, int& qh, int& ql) {
    float u = v * inv_sa;
    float qhf = rintf(u * 128.f);
    qhf = fminf(fmaxf(qhf, -127.f), 127.f);
    float r1 = u - qhf * 0.0078125f;            // 1/128
    float qlf = rintf(r1 * 16384.f);
    qlf = fminf(fmaxf(qlf, -127.f), 127.f);
    qh = (int)qhf;
    ql = (int)qlf;
}
__device__ __forceinline__ unsigned int pack4(int a, int b, int c, int d) {
    return (unsigned int)(a & 0xff) | ((unsigned int)(b & 0xff) << 8)
         | ((unsigned int)(c & 0xff) << 16) | ((unsigned int)(d & 0xff) << 24);
}

// ---------------------------- preprocessing ----------------------------
__global__ void zero_kernel() {
    for (int idx = blockIdx.x * blockDim.x + threadIdx.x; idx < NSEG;
         idx += gridDim.x * blockDim.x) g_cnt2[idx] = 0;
}

__global__ void hist_kernel(const int* __restrict__ ei, const int* __restrict__ et) {
    int idx = blockIdx.x * blockDim.x + threadIdx.x;
    if (idx >= E2) return;
    int dest, s;
    if (idx < N_EDGES) { dest = ei[idx]; s = et[idx]; }
    else { int e = idx - N_EDGES; dest = ei[N_EDGES + e]; s = et[e] + R_REL; }
    atomicAdd(&g_cnt2[dest * S_REL + s], 1);
}

__global__ void alpha_kernel() {
    int i = blockIdx.x * blockDim.x + threadIdx.x;
    if (i >= N_NODES) return;
    int cnt[S_REL];
    int tot = 0;
#pragma unroll
    for (int s = 0; s < S_REL; s++) { cnt[s] = g_cnt2[i * S_REL + s]; tot += cnt[s]; }
    g_ndeg[i] = tot;
    float suffix = 1.0f;
#pragma unroll
    for (int k = S_REL - 1; k >= 0; k--) {
        int s = (k >> 1) + R_REL * (k & 1);
        int c = cnt[s];
        float f = 2.0f / (float)(c > 0 ? c : 1);
        suffix *= f;
        g_alpha2[i * S_REL + s] = suffix;
        g_gamma2[i * S_REL + s] = suffix * (float)c;
    }
    g_A[i] = suffix;
}

// node-level scan (50k elements, 49 blocks)
__global__ void nscan1_kernel() {
    __shared__ int wsum[32];
    int b = blockIdx.x, t = threadIdx.x;
    int i = b * 1024 + t;
    int lane = t & 31, w = t >> 5;
    int v = (i < N_NODES) ? g_ndeg[i] : 0;
    int val = v;
#pragma unroll
    for (int d = 1; d < 32; d <<= 1) {
        int u = __shfl_up_sync(0xFFFFFFFF, val, d);
        if (lane >= d) val += u;
    }
    if (lane == 31) wsum[w] = val;
    __syncthreads();
    if (w == 0) {
        int x = wsum[lane];
#pragma unroll
        for (int d = 1; d < 32; d <<= 1) {
            int u = __shfl_up_sync(0xFFFFFFFF, x, d);
            if (lane >= d) x += u;
        }
        wsum[lane] = x;
    }
    __syncthreads();
    int incl = val + (w > 0 ? wsum[w - 1] : 0);
    if (i < N_NODES) g_noff[i + 1] = incl;
    if (t == 0) g_bsum[b] = wsum[31];
}
__global__ void nscan2_kernel(int nb) {
    int t = threadIdx.x, lane = t & 31;
    int v = (t < nb) ? g_bsum[t] : 0;
    int val = v;
#pragma unroll
    for (int d = 1; d < 32; d <<= 1) {
        int u = __shfl_up_sync(0xFFFFFFFF, val, d);
        if (lane >= d) val += u;
    }
    __shared__ int wsum[2];
    if (lane == 31 && t < 32) wsum[0] = val;
    __syncthreads();
    int add = (t >= 32) ? wsum[0] : 0;
    if (t < nb) g_boff[t] = val + add - v;   // exclusive
}
__global__ void nscan3_kernel() {
    int i = blockIdx.x * blockDim.x + threadIdx.x;
    if (i >= N_NODES) return;
    int end = g_noff[i + 1] + g_boff[i >> 10];
    int run = end - g_ndeg[i];
#pragma unroll
    for (int s = 0; s < S_REL; s++) {
        g_soff[i * S_REL + s] = run;
        g_cur2[i * S_REL + s] = run;
        run += g_cnt2[i * S_REL + s];
    }
    if (i == N_NODES - 1) g_soff[NSEG] = run;
}

__global__ void scatter_kernel(const int* __restrict__ ei, const int* __restrict__ et) {
    int idx = blockIdx.x * blockDim.x + threadIdx.x;
    if (idx >= E2) return;
    int dest, src, s;
    if (idx < N_EDGES) { dest = ei[idx]; src = ei[N_EDGES + idx]; s = et[idx]; }
    else { int e = idx - N_EDGES; dest = ei[N_EDGES + e]; src = ei[e]; s = et[e] + R_REL; }
    int pos = atomicAdd(&g_cur2[dest * S_REL + s], 1);
    g_rec[pos] = src;
}

// -------- weight quantization: per (layer, out-col j), K = 2560 --------
__global__ void __launch_bounds__(128) convw_kernel(const float* __restrict__ w,
                                                    const float* __restrict__ b) {
    __shared__ float red[128];
    int lj = blockIdx.x;              // 0..255
    int l = lj >> 7, j = lj & 127;
    int t = threadIdx.x;

    float vals[20];
    float m = 0.f;
#pragma unroll
    for (int p = 0; p < 20; p++) {
        int k = t * 20 + p;
        float v = 0.f;
        if (k < 2432) {
            int s = k >> 7, kk = k & 127;
            v = w[(((size_t)l * NW + s) * EMB + kk) * EMB + j];
        } else if (k < 2432 + NW) {
            v = b[((size_t)l * NW + (k - 2432)) * EMB + j];
        }
        vals[p] = v;
        m = fmaxf(m, fabsf(v));
    }
    red[t] = m;
    __syncthreads();
    for (int d = 64; d > 0; d >>= 1) {
        if (t < d) red[t] = fmaxf(red[t], red[t + d]);
        __syncthreads();
    }
    float sb = fmaxf(red[0], 1e-30f);
    if (t == 0) g_sb[l * EMB + j] = sb;
    float inv = 1.f / sb;

    size_t rbase = (size_t)(l * EMB + j) * KW + (size_t)t * 5;   // 20 vals = 5 words
#pragma unroll
    for (int wq = 0; wq < 5; wq++) {
        int qh[4], ql[4];
#pragma unroll
        for (int c = 0; c < 4; c++) quant2(vals[wq * 4 + c], inv, qh[c], ql[c]);
        g_Pbhi[rbase + wq] = pack4(qh[0], qh[1], qh[2], qh[3]);
        g_Pblo[rbase + wq] = pack4(ql[0], ql[1], ql[2], ql[3]);
    }
}

// ---------------- aggregation + row quantization (block-per-node) ----------------
// 256 threads per node; 10.25 KB static smem -> 8 blocks/SM.
__global__ void __launch_bounds__(256) agg_kernel(const float* __restrict__ X) {
    __shared__ float row[KTOT];
    __shared__ float red[8];
    int i = blockIdx.x;
    int tid = threadIdx.x, lane = tid & 31, w = tid >> 5;
    int fo = lane << 2;

#pragma unroll
    for (int t = 0; t < 3; t++) {
        int slot = w + 8 * t;
        if (slot < S_REL) {
            int sb = i * S_REL + slot;
            int e0 = g_soff[sb], e1 = g_soff[sb + 1];
            float al = g_alpha2[sb];
            float4 a = make_float4(0.f, 0.f, 0.f, 0.f);
            float4 a2 = make_float4(0.f, 0.f, 0.f, 0.f);
            int e = e0;
            for (; e + 1 < e1; e += 2) {
                int s0 = g_rec[e], s1 = g_rec[e + 1];
                float4 v0 = *(const float4*)(X + (size_t)s0 * EMB + fo);
                float4 v1 = *(const float4*)(X + (size_t)s1 * EMB + fo);
                a.x += v0.x; a.y += v0.y; a.z += v0.z; a.w += v0.w;
                a2.x += v1.x; a2.y += v1.y; a2.z += v1.z; a2.w += v1.w;
            }
            if (e < e1) {
                int s0 = g_rec[e];
                float4 v0 = *(const float4*)(X + (size_t)s0 * EMB + fo);
                a.x += v0.x; a.y += v0.y; a.z += v0.z; a.w += v0.w;
            }
            a.x += a2.x; a.y += a2.y; a.z += a2.z; a.w += a2.w;
            row[slot * 128 + fo + 0] = al * a.x;
            row[slot * 128 + fo + 1] = al * a.y;
            row[slot * 128 + fo + 2] = al * a.z;
            row[slot * 128 + fo + 3] = al * a.w;
        } else if (slot == S_REL) {         // self slot
            float Ai = g_A[i];
            float4 v = *(const float4*)(X + (size_t)i * EMB + fo);
            row[S_REL * 128 + fo + 0] = Ai * v.x;
            row[S_REL * 128 + fo + 1] = Ai * v.y;
            row[S_REL * 128 + fo + 2] = Ai * v.z;
            row[S_REL * 128 + fo + 3] = Ai * v.w;
        } else if (slot == NW) {            // bias block cols 2432..2559
#pragma unroll
            for (int c = 0; c < 4; c++) {
                int q = fo + c;
                float v = 0.f;
                if (q < S_REL)       v = g_gamma2[i * S_REL + q];
                else if (q == S_REL) v = g_A[i];
                row[2432 + q] = v;
            }
        }
    }
    __syncthreads();

    // block max |v| over 2560 = 256 * 10
    float m = 0.f;
#pragma unroll
    for (int p = 0; p < 10; p++) m = fmaxf(m, fabsf(row[tid * 10 + p]));
#pragma unroll
    for (int d = 16; d > 0; d >>= 1) m = fmaxf(m, __shfl_xor_sync(0xFFFFFFFF, m, d));
    if (lane == 0) red[w] = m;
    __syncthreads();
    float gm = red[0];
#pragma unroll
    for (int q = 1; q < 8; q++) gm = fmaxf(gm, red[q]);
    float sa = fmaxf(gm, 1e-30f);
    if (tid == 0) g_sa[i] = sa;
    float inv = 1.f / sa;

    // quantize + vectorized STG.128: KW4 = 160 uint4 per array
    uint4* Q4h = (uint4*)g_Qhi;
    uint4* Q4l = (uint4*)g_Qlo;
    size_t rb4 = (size_t)i * KW4;
    for (int g = tid; g < KW4; g += 256) {
        const float* v16 = row + g * 16;
        unsigned int wh[4], wl[4];
#pragma unroll
        for (int wq = 0; wq < 4; wq++) {
            int qh[4], ql[4];
#pragma unroll
            for (int c = 0; c < 4; c++) quant2(v16[wq * 4 + c], inv, qh[c], ql[c]);
            wh[wq] = pack4(qh[0], qh[1], qh[2], qh[3]);
            wl[wq] = pack4(ql[0], ql[1], ql[2], ql[3]);
        }
        Q4h[rb4 + g] = make_uint4(wh[0], wh[1], wh[2], wh[3]);
        Q4l[rb4 + g] = make_uint4(wl[0], wl[1], wl[2], wl[3]);
    }
}

// --------------------------- int8 streaming GEMM (R8-exact) ---------------------------
__device__ __forceinline__ void fill_stage(uint32_t sbase, int k0, int m0, int tid,
                                           const char* __restrict__ Bh,
                                           const char* __restrict__ Bl) {
    const char* Ah = (const char*)g_Qhi;
    const char* Al = (const char*)g_Qlo;
#pragma unroll
    for (int p = 0; p < 4; p++) {
        int idx = tid + p * 256;          // 0..1023
        int rrow = idx >> 3, c = idx & 7; // 8 x 16B per 128B row
        uint32_t d = (uint32_t)(rrow * SROW2 + c * 16);
        size_t asrc = (size_t)(m0 + rrow) * KTOT + k0 + c * 16;
        cp_async16(sbase + OFF_AHI + d, Ah + asrc);
        cp_async16(sbase + OFF_ALO + d, Al + asrc);
        size_t bsrc = (size_t)rrow * KTOT + k0 + c * 16;
        cp_async16(sbase + OFF_BHI + d, Bh + bsrc);
        cp_async16(sbase + OFF_BLO + d, Bl + bsrc);
    }
}

__global__ void __launch_bounds__(256) gemm8_kernel(float* __restrict__ Out,
                                                    int layer, int do_relu) {
    extern __shared__ char dsm[];
    uint32_t sb = smem_u32(dsm);
    int tid = threadIdx.x, wid = tid >> 5, lane = tid & 31;
    int warp_m = wid & 1;
    int warp_n = wid >> 1;

    const char* Bh = (const char*)g_Pbhi + (size_t)layer * EMB * KTOT;
    const char* Bl = (const char*)g_Pblo + (size_t)layer * EMB * KTOT;

    uint32_t a_off = (uint32_t)((warp_m * 64 + (lane & 15)) * SROW2 + (lane >> 4) * 16);
    int bm = lane >> 3;
    uint32_t b_row = (uint32_t)(warp_n * 32 + ((bm >> 1) << 3) + (lane & 7));
    uint32_t b_koff = (uint32_t)((bm & 1) * 16);

    int m0 = blockIdx.x * 128;

    int acc1[4][4][4], acc2[4][4][4];
#pragma unroll
    for (int mi = 0; mi < 4; mi++)
#pragma unroll
        for (int ni = 0; ni < 4; ni++)
#pragma unroll
            for (int q = 0; q < 4; q++) { acc1[mi][ni][q] = 0; acc2[mi][ni][q] = 0; }

    fill_stage(sb, 0, m0, tid, Bh, Bl);
    CP_COMMIT();

    for (int u = 0; u < NCH; u++) {
        if (u + 1 < NCH) {
            fill_stage(sb + ((u + 1) & 1) * STAGE_SZ, (u + 1) * 128, m0, tid, Bh, Bl);
            CP_COMMIT();
            CP_WAIT1();
        } else {
            CP_WAIT0();
        }
        __syncthreads();

        uint32_t st = sb + (u & 1) * STAGE_SZ;
#pragma unroll
        for (int ks = 0; ks < 4; ks++) {            // k = 32 int8 per step
            uint32_t k2 = (uint32_t)(ks * 32);
            uint32_t Ah4[4][4], Al4[4][4];
#pragma unroll
            for (int mi = 0; mi < 4; mi++) {
                uint32_t ad = st + OFF_AHI + a_off + (uint32_t)(mi * 16 * SROW2) + k2;
                ldsm_x4(Ah4[mi], ad);
                ldsm_x4(Al4[mi], ad + (OFF_ALO - OFF_AHI));
            }
            uint32_t Bh4[4][2], Bl4[4][2];
#pragma unroll
            for (int nj = 0; nj < 2; nj++) {
                uint32_t bd = st + OFF_BHI + (b_row + nj * 16) * SROW2 + b_koff + k2;
                uint32_t r4[4];
                ldsm_x4(r4, bd);
                Bh4[nj * 2][0] = r4[0]; Bh4[nj * 2][1] = r4[1];
                Bh4[nj * 2 + 1][0] = r4[2]; Bh4[nj * 2 + 1][1] = r4[3];
                ldsm_x4(r4, bd + (OFF_BLO - OFF_BHI));
                Bl4[nj * 2][0] = r4[0]; Bl4[nj * 2][1] = r4[1];
                Bl4[nj * 2 + 1][0] = r4[2]; Bl4[nj * 2 + 1][1] = r4[3];
            }
#pragma unroll
            for (int mi = 0; mi < 4; mi++)
#pragma unroll
                for (int ni = 0; ni < 4; ni++) {
                    mma_s8(acc1[mi][ni], Ah4[mi], Bh4[ni]);
                    mma_s8(acc2[mi][ni], Ah4[mi], Bl4[ni]);
                    mma_s8(acc2[mi][ni], Al4[mi], Bh4[ni]);
                }
        }
        __syncthreads();
    }

    // epilogue: dequant + write
    int rbase = m0 + warp_m * 64 + (lane >> 2);
    int cbase = warp_n * 32 + (lane & 3) * 2;
    const float* sbp = g_sb + layer * EMB;
#pragma unroll
    for (int mi = 0; mi < 4; mi++) {
        int r = rbase + mi * 16;
#pragma unroll
        for (int ni = 0; ni < 4; ni++) {
            int c = cbase + ni * 8;
            float sb0 = sbp[c], sb1 = sbp[c + 1];
            if (r < N_NODES) {
                float sar = g_sa[r];
                float vx = sar * sb0 * ((float)acc1[mi][ni][0] * S1 + (float)acc2[mi][ni][0] * S2);
                float vy = sar * sb1 * ((float)acc1[mi][ni][1] * S1 + (float)acc2[mi][ni][1] * S2);
                if (do_relu) { vx = fmaxf(vx, 0.f); vy = fmaxf(vy, 0.f); }
                *(float2*)(Out + (size_t)r * EMB + c) = make_float2(vx, vy);
            }
            if (r + 8 < N_NODES) {
                float sar = g_sa[r + 8];
                float vx = sar * sb0 * ((float)acc1[mi][ni][2] * S1 + (float)acc2[mi][ni][2] * S2);
                float vy = sar * sb1 * ((float)acc1[mi][ni][3] * S1 + (float)acc2[mi][ni][3] * S2);
                if (do_relu) { vx = fmaxf(vx, 0.f); vy = fmaxf(vy, 0.f); }
                *(float2*)(Out + (size_t)(r + 8) * EMB + c) = make_float2(vx, vy);
            }
        }
    }
}

// ------------------------------ launch ---------------------------------
extern "C" void kernel_launch(void* const* d_in, const int* in_sizes, int n_in,
                              void* d_out, int out_size) {
    const int*   ei  = (const int*)d_in[0];     // [2, E]
    const int*   et  = (const int*)d_in[1];     // [E]
    const float* emb = (const float*)d_in[2];   // [N, 128]
    const float* w   = (const float*)d_in[3];   // [2, 19, 128, 128]
    const float* b   = (const float*)d_in[4];   // [2, 19, 128]
    float* out = (float*)d_out;

    float* hptr = nullptr;
    cudaGetSymbolAddress((void**)&hptr, g_H);

    cudaFuncSetAttribute(gemm8_kernel,
                         cudaFuncAttributeMaxDynamicSharedMemorySize, GEMM_DSM);

    zero_kernel<<<512, 256>>>();
    hist_kernel<<<(E2 + 255) / 256, 256>>>(ei, et);
    alpha_kernel<<<(N_NODES + 255) / 256, 256>>>();
    int nb = (N_NODES + 1023) / 1024;   // 49
    nscan1_kernel<<<nb, 1024>>>();
    nscan2_kernel<<<1, 64>>>(nb);
    nscan3_kernel<<<(N_NODES + 255) / 256, 256>>>();
    scatter_kernel<<<(E2 + 255) / 256, 256>>>(ei, et);
    convw_kernel<<<2 * EMB, 128>>>(w, b);

    // layer 0: emb -> H (relu)
    agg_kernel<<<N_NODES, 256>>>(emb);
    gemm8_kernel<<<TILES_M, 256, GEMM_DSM>>>(hptr, 0, 1);
    // layer 1: H -> out
    agg_kernel<<<N_NODES, 256>>>(hptr);
    gemm8_kernel<<<TILES_M, 256, GEMM_DSM>>>(out, 1, 0);
}

// round 11
// speedup vs baseline: 1.0023x; 1.0023x over previous
#include <cuda_runtime.h>
#include <cuda_bf16.h>
#include <cstdint>

#define N_NODES 50000
#define NPAD    50048             // 391*128
#define EMB     128
#define R_REL   9
#define S_REL   18
#define NW      19
#define N_EDGES 800000
#define E2      (2*N_EDGES)
#define NSEG    (S_REL*N_NODES)   // 900000
#define KTOT    2560              // 19*128 + 128 (bias block padded to 128)
#define KW      640               // KTOT/4 packed words per row
#define NCH     20                // K chunks of 128
#define TILES_M 391

// smem: 4 int8 arrays (Ahi,Alo,Bhi,Blo) x 2 stages; 128 rows x 128 s8, stride 144
#define SROW2   144
#define ATILE2  18432             // 128*144
#define STAGE_SZ (4*ATILE2)       // 73728
#define OFF_AHI 0
#define OFF_ALO ATILE2
#define OFF_BHI (2*ATILE2)
#define OFF_BLO (3*ATILE2)
#define GEMM_DSM (2*STAGE_SZ)     // 147456

#define S1 6.103515625e-5f        // 2^-14
#define S2 4.76837158203125e-7f   // 2^-21

// -------- scratch (device globals) --------
__device__ int   g_cnt2[NSEG];
__device__ float g_alpha2[NSEG];
__device__ float g_gamma2[NSEG];
__device__ float g_A[N_NODES];
__device__ int   g_soff[NSEG];    // per-segment start (atomic-allocated regions)
__device__ int   g_cur2[NSEG];
__device__ int   g_total;
__device__ int   g_rec[E2];
__device__ float g_H[(size_t)N_NODES * EMB];
__device__ unsigned int g_Qhi[(size_t)NPAD * KW];    // ~128 MB
__device__ unsigned int g_Qlo[(size_t)NPAD * KW];    // ~128 MB
__device__ unsigned int g_Pbhi[2 * EMB * KW];
__device__ unsigned int g_Pblo[2 * EMB * KW];
__device__ float g_sa[N_NODES];
__device__ float g_sb[2 * EMB];

// ------------------------- PTX helpers -------------------------
__device__ __forceinline__ uint32_t smem_u32(const void* p) {
    uint32_t a;
    asm("{ .reg .u64 t; cvta.to.shared.u64 t, %1; cvt.u32.u64 %0, t; }" : "=r"(a) : "l"(p));
    return a;
}
__device__ __forceinline__ void cp_async16(uint32_t dst, const void* src) {
    asm volatile("cp.async.cg.shared.global [%0], [%1], 16;"
                 :: "r"(dst), "l"(src) : "memory");
}
#define CP_COMMIT() asm volatile("cp.async.commit_group;" ::: "memory")
#define CP_WAIT1()  asm volatile("cp.async.wait_group 1;" ::: "memory")
#define CP_WAIT0()  asm volatile("cp.async.wait_group 0;" ::: "memory")

__device__ __forceinline__ void ldsm_x4(uint32_t* r, uint32_t addr) {
    asm volatile("ldmatrix.sync.aligned.m8n8.x4.shared.b16 {%0,%1,%2,%3}, [%4];"
                 : "=r"(r[0]), "=r"(r[1]), "=r"(r[2]), "=r"(r[3]) : "r"(addr));
}
__device__ __forceinline__ void mma_s8(int* c, const uint32_t* a, const uint32_t* b) {
    asm volatile("mma.sync.aligned.m16n8k32.row.col.s32.s8.s8.s32 "
                 "{%0,%1,%2,%3}, {%4,%5,%6,%7}, {%8,%9}, {%0,%1,%2,%3};"
                 : "+r"(c[0]), "+r"(c[1]), "+r"(c[2]), "+r"(c[3])
                 : "r"(a[0]), "r"(a[1]), "r"(a[2]), "r"(a[3]), "r"(b[0]), "r"(b[1]));
}

__device__ __forceinline__ void quant2(float v, float inv_sa, int& qh, int& ql) {
    float u = v * inv_sa;
    float qhf = rintf(u * 128.f);
    qhf = fminf(fmaxf(qhf, -127.f), 127.f);
    float r1 = u - qhf * 0.0078125f;            // 1/128
    float qlf = rintf(r1 * 16384.f);
    qlf = fminf(fmaxf(qlf, -127.f), 127.f);
    qh = (int)qhf;
    ql = (int)qlf;
}
__device__ __forceinline__ unsigned int pack4(int a, int b, int c, int d) {
    return (unsigned int)(a & 0xff) | ((unsigned int)(b & 0xff) << 8)
         | ((unsigned int)(c & 0xff) << 16) | ((unsigned int)(d & 0xff) << 24);
}

// ---------------------------- preprocessing ----------------------------
__global__ void hist_kernel(const int* __restrict__ ei, const int* __restrict__ et) {
    int idx = blockIdx.x * blockDim.x + threadIdx.x;
    if (idx >= E2) return;
    int dest, s;
    if (idx < N_EDGES) { dest = ei[idx]; s = et[idx]; }
    else { int e = idx - N_EDGES; dest = ei[N_EDGES + e]; s = et[e] + R_REL; }
    atomicAdd(&g_cnt2[dest * S_REL + s], 1);
}

// alpha + suffix products + atomic region allocation (replaces the scans)
__global__ void alpha_kernel() {
    int i = blockIdx.x * blockDim.x + threadIdx.x;
    if (i >= N_NODES) return;
    int cnt[S_REL];
    int tot = 0;
#pragma unroll
    for (int s = 0; s < S_REL; s++) { cnt[s] = g_cnt2[i * S_REL + s]; tot += cnt[s]; }
    float suffix = 1.0f;
#pragma unroll
    for (int k = S_REL - 1; k >= 0; k--) {
        int s = (k >> 1) + R_REL * (k & 1);
        int c = cnt[s];
        float f = 2.0f / (float)(c > 0 ? c : 1);
        suffix *= f;
        g_alpha2[i * S_REL + s] = suffix;
        g_gamma2[i * S_REL + s] = suffix * (float)c;
    }
    g_A[i] = suffix;
    int run = atomicAdd(&g_total, tot);
#pragma unroll
    for (int s = 0; s < S_REL; s++) {
        g_soff[i * S_REL + s] = run;
        g_cur2[i * S_REL + s] = run;
        run += cnt[s];
    }
}

__global__ void scatter_kernel(const int* __restrict__ ei, const int* __restrict__ et) {
    int idx = blockIdx.x * blockDim.x + threadIdx.x;
    if (idx >= E2) return;
    int dest, src, s;
    if (idx < N_EDGES) { dest = ei[idx]; src = ei[N_EDGES + idx]; s = et[idx]; }
    else { int e = idx - N_EDGES; dest = ei[N_EDGES + e]; src = ei[e]; s = et[e] + R_REL; }
    int pos = atomicAdd(&g_cur2[dest * S_REL + s], 1);
    g_rec[pos] = src;
}

// -------- weight quantization: per (layer, out-col j), K = 2560 --------
__global__ void __launch_bounds__(128) convw_kernel(const float* __restrict__ w,
                                                    const float* __restrict__ b) {
    __shared__ float red[128];
    int lj = blockIdx.x;              // 0..255
    int l = lj >> 7, j = lj & 127;
    int t = threadIdx.x;

    float vals[20];
    float m = 0.f;
#pragma unroll
    for (int p = 0; p < 20; p++) {
        int k = t * 20 + p;
        float v = 0.f;
        if (k < 2432) {
            int s = k >> 7, kk = k & 127;
            v = w[(((size_t)l * NW + s) * EMB + kk) * EMB + j];
        } else if (k < 2432 + NW) {
            v = b[((size_t)l * NW + (k - 2432)) * EMB + j];
        }
        vals[p] = v;
        m = fmaxf(m, fabsf(v));
    }
    red[t] = m;
    __syncthreads();
    for (int d = 64; d > 0; d >>= 1) {
        if (t < d) red[t] = fmaxf(red[t], red[t + d]);
        __syncthreads();
    }
    float sb = fmaxf(red[0], 1e-30f);
    if (t == 0) g_sb[l * EMB + j] = sb;
    float inv = 1.f / sb;

    size_t rbase = (size_t)(l * EMB + j) * KW + (size_t)t * 5;   // 20 vals = 5 words
#pragma unroll
    for (int wq = 0; wq < 5; wq++) {
        int qh[4], ql[4];
#pragma unroll
        for (int c = 0; c < 4; c++) quant2(vals[wq * 4 + c], inv, qh[c], ql[c]);
        g_Pbhi[rbase + wq] = pack4(qh[0], qh[1], qh[2], qh[3]);
        g_Pblo[rbase + wq] = pack4(ql[0], ql[1], ql[2], ql[3]);
    }
}

// ---------------- aggregation + row quantization (block-per-node, R8-exact) ----------------
__global__ void __launch_bounds__(256) agg_kernel(const float* __restrict__ X) {
    __shared__ float row[KTOT];
    __shared__ float red[8];
    int i = blockIdx.x;
    int tid = threadIdx.x, lane = tid & 31, w = tid >> 5;
    int fo = lane << 2;

#pragma unroll
    for (int t = 0; t < 3; t++) {
        int slot = w + 8 * t;
        if (slot < S_REL) {
            int sb = i * S_REL + slot;
            int e0 = g_soff[sb];
            int e1 = e0 + g_cnt2[sb];
            float al = g_alpha2[sb];
            float4 a = make_float4(0.f, 0.f, 0.f, 0.f);
            for (int e = e0; e < e1; e++) {
                int src = g_rec[e];
                float4 v = *(const float4*)(X + (size_t)src * EMB + fo);
                a.x += v.x; a.y += v.y; a.z += v.z; a.w += v.w;
            }
            row[slot * 128 + fo + 0] = al * a.x;
            row[slot * 128 + fo + 1] = al * a.y;
            row[slot * 128 + fo + 2] = al * a.z;
            row[slot * 128 + fo + 3] = al * a.w;
        } else if (slot == S_REL) {         // self slot
            float Ai = g_A[i];
            float4 v = *(const float4*)(X + (size_t)i * EMB + fo);
            row[S_REL * 128 + fo + 0] = Ai * v.x;
            row[S_REL * 128 + fo + 1] = Ai * v.y;
            row[S_REL * 128 + fo + 2] = Ai * v.z;
            row[S_REL * 128 + fo + 3] = Ai * v.w;
        } else if (slot == NW) {            // bias block cols 2432..2559
#pragma unroll
            for (int c = 0; c < 4; c++) {
                int q = fo + c;
                float v = 0.f;
                if (q < S_REL)       v = g_gamma2[i * S_REL + q];
                else if (q == S_REL) v = g_A[i];
                row[2432 + q] = v;
            }
        }
    }
    __syncthreads();

    // block max |v| over 2560 = 256 * 10
    float m = 0.f;
#pragma unroll
    for (int p = 0; p < 10; p++) m = fmaxf(m, fabsf(row[tid * 10 + p]));
#pragma unroll
    for (int d = 16; d > 0; d >>= 1) m = fmaxf(m, __shfl_xor_sync(0xFFFFFFFF, m, d));
    if (lane == 0) red[w] = m;
    __syncthreads();
    float gm = red[0];
#pragma unroll
    for (int q = 1; q < 8; q++) gm = fmaxf(gm, red[q]);
    float sa = fmaxf(gm, 1e-30f);
    if (tid == 0) g_sa[i] = sa;
    float inv = 1.f / sa;

    // quantize: KW = 640 words with 256 threads (R8-exact access pattern)
    size_t rbase = (size_t)i * KW;
    for (int wq = tid; wq < KW; wq += 256) {
        const float* v4 = row + wq * 4;
        int qh[4], ql[4];
#pragma unroll
        for (int c = 0; c < 4; c++) quant2(v4[c], inv, qh[c], ql[c]);
        g_Qhi[rbase + wq] = pack4(qh[0], qh[1], qh[2], qh[3]);
        g_Qlo[rbase + wq] = pack4(ql[0], ql[1], ql[2], ql[3]);
    }
}

// --------------------------- int8 streaming GEMM (R8-exact) ---------------------------
__device__ __forceinline__ void fill_stage(uint32_t sbase, int k0, int m0, int tid,
                                           const char* __restrict__ Bh,
                                           const char* __restrict__ Bl) {
    const char* Ah = (const char*)g_Qhi;
    const char* Al = (const char*)g_Qlo;
#pragma unroll
    for (int p = 0; p < 4; p++) {
        int idx = tid + p * 256;          // 0..1023
        int rrow = idx >> 3, c = idx & 7; // 8 x 16B per 128B row
        uint32_t d = (uint32_t)(rrow * SROW2 + c * 16);
        size_t asrc = (size_t)(m0 + rrow) * KTOT + k0 + c * 16;
        cp_async16(sbase + OFF_AHI + d, Ah + asrc);
        cp_async16(sbase + OFF_ALO + d, Al + asrc);
        size_t bsrc = (size_t)rrow * KTOT + k0 + c * 16;
        cp_async16(sbase + OFF_BHI + d, Bh + bsrc);
        cp_async16(sbase + OFF_BLO + d, Bl + bsrc);
    }
}

__global__ void __launch_bounds__(256) gemm8_kernel(float* __restrict__ Out,
                                                    int layer, int do_relu) {
    extern __shared__ char dsm[];
    uint32_t sb = smem_u32(dsm);
    int tid = threadIdx.x, wid = tid >> 5, lane = tid & 31;
    int warp_m = wid & 1;
    int warp_n = wid >> 1;

    const char* Bh = (const char*)g_Pbhi + (size_t)layer * EMB * KTOT;
    const char* Bl = (const char*)g_Pblo + (size_t)layer * EMB * KTOT;

    uint32_t a_off = (uint32_t)((warp_m * 64 + (lane & 15)) * SROW2 + (lane >> 4) * 16);
    int bm = lane >> 3;
    uint32_t b_row = (uint32_t)(warp_n * 32 + ((bm >> 1) << 3) + (lane & 7));
    uint32_t b_koff = (uint32_t)((bm & 1) * 16);

    int m0 = blockIdx.x * 128;

    int acc1[4][4][4], acc2[4][4][4];
#pragma unroll
    for (int mi = 0; mi < 4; mi++)
#pragma unroll
        for (int ni = 0; ni < 4; ni++)
#pragma unroll
            for (int q = 0; q < 4; q++) { acc1[mi][ni][q] = 0; acc2[mi][ni][q] = 0; }

    fill_stage(sb, 0, m0, tid, Bh, Bl);
    CP_COMMIT();

    for (int u = 0; u < NCH; u++) {
        if (u + 1 < NCH) {
            fill_stage(sb + ((u + 1) & 1) * STAGE_SZ, (u + 1) * 128, m0, tid, Bh, Bl);
            CP_COMMIT();
            CP_WAIT1();
        } else {
            CP_WAIT0();
        }
        __syncthreads();

        uint32_t st = sb + (u & 1) * STAGE_SZ;
#pragma unroll
        for (int ks = 0; ks < 4; ks++) {            // k = 32 int8 per step
            uint32_t k2 = (uint32_t)(ks * 32);
            uint32_t Ah4[4][4], Al4[4][4];
#pragma unroll
            for (int mi = 0; mi < 4; mi++) {
                uint32_t ad = st + OFF_AHI + a_off + (uint32_t)(mi * 16 * SROW2) + k2;
                ldsm_x4(Ah4[mi], ad);
                ldsm_x4(Al4[mi], ad + (OFF_ALO - OFF_AHI));
            }
            uint32_t Bh4[4][2], Bl4[4][2];
#pragma unroll
            for (int nj = 0; nj < 2; nj++) {
                uint32_t bd = st + OFF_BHI + (b_row + nj * 16) * SROW2 + b_koff + k2;
                uint32_t r4[4];
                ldsm_x4(r4, bd);
                Bh4[nj * 2][0] = r4[0]; Bh4[nj * 2][1] = r4[1];
                Bh4[nj * 2 + 1][0] = r4[2]; Bh4[nj * 2 + 1][1] = r4[3];
                ldsm_x4(r4, bd + (OFF_BLO - OFF_BHI));
                Bl4[nj * 2][0] = r4[0]; Bl4[nj * 2][1] = r4[1];
                Bl4[nj * 2 + 1][0] = r4[2]; Bl4[nj * 2 + 1][1] = r4[3];
            }
#pragma unroll
            for (int mi = 0; mi < 4; mi++)
#pragma unroll
                for (int ni = 0; ni < 4; ni++) {
                    mma_s8(acc1[mi][ni], Ah4[mi], Bh4[ni]);
                    mma_s8(acc2[mi][ni], Ah4[mi], Bl4[ni]);
                    mma_s8(acc2[mi][ni], Al4[mi], Bh4[ni]);
                }
        }
        __syncthreads();
    }

    // epilogue: dequant + write
    int rbase = m0 + warp_m * 64 + (lane >> 2);
    int cbase = warp_n * 32 + (lane & 3) * 2;
    const float* sbp = g_sb + layer * EMB;
#pragma unroll
    for (int mi = 0; mi < 4; mi++) {
        int r = rbase + mi * 16;
#pragma unroll
        for (int ni = 0; ni < 4; ni++) {
            int c = cbase + ni * 8;
            float sb0 = sbp[c], sb1 = sbp[c + 1];
            if (r < N_NODES) {
                float sar = g_sa[r];
                float vx = sar * sb0 * ((float)acc1[mi][ni][0] * S1 + (float)acc2[mi][ni][0] * S2);
                float vy = sar * sb1 * ((float)acc1[mi][ni][1] * S1 + (float)acc2[mi][ni][1] * S2);
                if (do_relu) { vx = fmaxf(vx, 0.f); vy = fmaxf(vy, 0.f); }
                *(float2*)(Out + (size_t)r * EMB + c) = make_float2(vx, vy);
            }
            if (r + 8 < N_NODES) {
                float sar = g_sa[r + 8];
                float vx = sar * sb0 * ((float)acc1[mi][ni][2] * S1 + (float)acc2[mi][ni][2] * S2);
                float vy = sar * sb1 * ((float)acc1[mi][ni][3] * S1 + (float)acc2[mi][ni][3] * S2);
                if (do_relu) { vx = fmaxf(vx, 0.f); vy = fmaxf(vy, 0.f); }
                *(float2*)(Out + (size_t)(r + 8) * EMB + c) = make_float2(vx, vy);
            }
        }
    }
}

// ------------------------------ launch ---------------------------------
extern "C" void kernel_launch(void* const* d_in, const int* in_sizes, int n_in,
                              void* d_out, int out_size) {
    const int*   ei  = (const int*)d_in[0];     // [2, E]
    const int*   et  = (const int*)d_in[1];     // [E]
    const float* emb = (const float*)d_in[2];   // [N, 128]
    const float* w   = (const float*)d_in[3];   // [2, 19, 128, 128]
    const float* b   = (const float*)d_in[4];   // [2, 19, 128]
    float* out = (float*)d_out;

    float* hptr = nullptr;
    cudaGetSymbolAddress((void**)&hptr, g_H);
    void* cntptr = nullptr;
    cudaGetSymbolAddress(&cntptr, g_cnt2);
    void* totptr = nullptr;
    cudaGetSymbolAddress(&totptr, g_total);

    cudaFuncSetAttribute(gemm8_kernel,
                         cudaFuncAttributeMaxDynamicSharedMemorySize, GEMM_DSM);

    cudaMemsetAsync(cntptr, 0, NSEG * sizeof(int));
    cudaMemsetAsync(totptr, 0, sizeof(int));
    hist_kernel<<<(E2 + 255) / 256, 256>>>(ei, et);
    alpha_kernel<<<(N_NODES + 255) / 256, 256>>>();
    scatter_kernel<<<(E2 + 255) / 256, 256>>>(ei, et);

    // layer 0: emb -> H (relu)  (agg is early in launch order for ncu capture)
    agg_kernel<<<N_NODES, 256>>>(emb);
    convw_kernel<<<2 * EMB, 128>>>(w, b);
    gemm8_kernel<<<TILES_M, 256, GEMM_DSM>>>(hptr, 0, 1);
    // layer 1: H -> out
    agg_kernel<<<N_NODES, 256>>>(hptr);
    gemm8_kernel<<<TILES_M, 256, GEMM_DSM>>>(out, 1, 0);
}

// round 12
// speedup vs baseline: 1.0981x; 1.0956x over previous
#include <cuda_runtime.h>
#include <cuda_bf16.h>
#include <cstdint>

#define N_NODES 50000
#define NPAD    50048             // 391*128
#define EMB     128
#define R_REL   9
#define S_REL   18
#define NW      19
#define N_EDGES 800000
#define E2      (2*N_EDGES)
#define NSEG    (S_REL*N_NODES)   // 900000
#define KTOT    2560              // 19*128 + 128 (bias block padded to 128)
#define KW      640               // KTOT/4 packed words per row
#define NCH     20                // K chunks of 128
#define TILES_M 391

// smem: 4 int8 arrays (Ahi,Alo,Bhi,Blo) x 2 stages; 128 rows x 128 s8, stride 144
#define SROW2   144
#define ATILE2  18432             // 128*144
#define STAGE_SZ (4*ATILE2)       // 73728
#define OFF_AHI 0
#define OFF_ALO ATILE2
#define OFF_BHI (2*ATILE2)
#define OFF_BLO (3*ATILE2)
#define GEMM_DSM (2*STAGE_SZ)     // 147456

#define S1 6.103515625e-5f        // 2^-14
#define S2 4.76837158203125e-7f   // 2^-21

// -------- scratch (device globals) --------
__device__ int   g_cnt2[NSEG];
__device__ float g_alpha2[NSEG];
__device__ float g_gamma2[NSEG];
__device__ float g_A[N_NODES];
__device__ int   g_soff[NSEG + 1];
__device__ int   g_cur2[NSEG];
__device__ int   g_bsum[1024];
__device__ int   g_boff[1024];
__device__ int   g_rec[E2];
__device__ float g_H[(size_t)N_NODES * EMB];
__device__ unsigned int g_Qhi[(size_t)NPAD * KW];    // ~128 MB
__device__ unsigned int g_Qlo[(size_t)NPAD * KW];    // ~128 MB
__device__ unsigned int g_Pbhi[2 * EMB * KW];
__device__ unsigned int g_Pblo[2 * EMB * KW];
__device__ float g_sa[N_NODES];
__device__ float g_sb[2 * EMB];

// ------------------------- PTX helpers -------------------------
__device__ __forceinline__ uint32_t smem_u32(const void* p) {
    uint32_t a;
    asm("{ .reg .u64 t; cvta.to.shared.u64 t, %1; cvt.u32.u64 %0, t; }" : "=r"(a) : "l"(p));
    return a;
}
__device__ __forceinline__ void cp_async16(uint32_t dst, const void* src) {
    asm volatile("cp.async.cg.shared.global [%0], [%1], 16;"
                 :: "r"(dst), "l"(src) : "memory");
}
#define CP_COMMIT() asm volatile("cp.async.commit_group;" ::: "memory")
#define CP_WAIT1()  asm volatile("cp.async.wait_group 1;" ::: "memory")
#define CP_WAIT0()  asm volatile("cp.async.wait_group 0;" ::: "memory")

__device__ __forceinline__ void ldsm_x4(uint32_t* r, uint32_t addr) {
    asm volatile("ldmatrix.sync.aligned.m8n8.x4.shared.b16 {%0,%1,%2,%3}, [%4];"
                 : "=r"(r[0]), "=r"(r[1]), "=r"(r[2]), "=r"(r[3]) : "r"(addr));
}
__device__ __forceinline__ void mma_s8(int* c, const uint32_t* a, const uint32_t* b) {
    asm volatile("mma.sync.aligned.m16n8k32.row.col.s32.s8.s8.s32 "
                 "{%0,%1,%2,%3}, {%4,%5,%6,%7}, {%8,%9}, {%0,%1,%2,%3};"
                 : "+r"(c[0]), "+r"(c[1]), "+r"(c[2]), "+r"(c[3])
                 : "r"(a[0]), "r"(a[1]), "r"(a[2]), "r"(a[3]), "r"(b[0]), "r"(b[1]));
}

// original (convw-side) quantizer — unchanged
__device__ __forceinline__ void quant2(float v, float inv_sa, int& qh, int& ql) {
    float u = v * inv_sa;
    float qhf = rintf(u * 128.f);
    qhf = fminf(fmaxf(qhf, -127.f), 127.f);
    float r1 = u - qhf * 0.0078125f;            // 1/128
    float qlf = rintf(r1 * 16384.f);
    qlf = fminf(fmaxf(qlf, -127.f), 127.f);
    qh = (int)qhf;
    ql = (int)qlf;
}
__device__ __forceinline__ unsigned int pack4(int a, int b, int c, int d) {
    return (unsigned int)(a & 0xff) | ((unsigned int)(b & 0xff) << 8)
         | ((unsigned int)(c & 0xff) << 16) | ((unsigned int)(d & 0xff) << 24);
}

// fast agg-side quantizer: fewer clamps + CVT.RNI + PRMT packing
__device__ __forceinline__ unsigned int prmt_pack(int a, int b, int c, int d) {
    unsigned int p01 = __byte_perm((unsigned int)a, (unsigned int)b, 0x0040);
    unsigned int p23 = __byte_perm((unsigned int)c, (unsigned int)d, 0x0040);
    return __byte_perm(p01, p23, 0x5410);
}
__device__ __forceinline__ void quant_fast(float v, float inv_sa, int& qh, int& ql) {
    float u = v * inv_sa;                         // |u| <= 1
    float s = fminf(fmaxf(u * 128.f, -127.f), 127.f);
    float qhf = rintf(s);
    qh = (int)qhf;
    float r1 = fmaf(qhf, -0.0078125f, u);
    ql = min(__float2int_rn(r1 * 16384.f), 127);  // low clamp unneeded (-128 fits s8)
}

// ---------------------------- preprocessing (R8-exact) ----------------------------
__global__ void zero_kernel() {
    for (int idx = blockIdx.x * blockDim.x + threadIdx.x; idx < NSEG;
         idx += gridDim.x * blockDim.x) g_cnt2[idx] = 0;
}

__global__ void hist_kernel(const int* __restrict__ ei, const int* __restrict__ et) {
    int idx = blockIdx.x * blockDim.x + threadIdx.x;
    if (idx >= E2) return;
    int dest, s;
    if (idx < N_EDGES) { dest = ei[idx]; s = et[idx]; }
    else { int e = idx - N_EDGES; dest = ei[N_EDGES + e]; s = et[e] + R_REL; }
    atomicAdd(&g_cnt2[dest * S_REL + s], 1);
}

__global__ void alpha_kernel() {
    int i = blockIdx.x * blockDim.x + threadIdx.x;
    if (i >= N_NODES) return;
    int cnt[S_REL];
#pragma unroll
    for (int s = 0; s < S_REL; s++) cnt[s] = g_cnt2[i * S_REL + s];
    float suffix = 1.0f;
#pragma unroll
    for (int k = S_REL - 1; k >= 0; k--) {
        int s = (k >> 1) + R_REL * (k & 1);
        int c = cnt[s];
        float f = 2.0f / (float)(c > 0 ? c : 1);
        suffix *= f;
        g_alpha2[i * S_REL + s] = suffix;
        g_gamma2[i * S_REL + s] = suffix * (float)c;
    }
    g_A[i] = suffix;
}

__global__ void scan1_kernel() {
    __shared__ int wsum[32];
    int b = blockIdx.x, t = threadIdx.x;
    int i = b * 1024 + t;
    int lane = t & 31, w = t >> 5;
    int v = (i < NSEG) ? g_cnt2[i] : 0;
    int val = v;
#pragma unroll
    for (int d = 1; d < 32; d <<= 1) {
        int u = __shfl_up_sync(0xFFFFFFFF, val, d);
        if (lane >= d) val += u;
    }
    if (lane == 31) wsum[w] = val;
    __syncthreads();
    if (w == 0) {
        int x = wsum[lane];
#pragma unroll
        for (int d = 1; d < 32; d <<= 1) {
            int u = __shfl_up_sync(0xFFFFFFFF, x, d);
            if (lane >= d) x += u;
        }
        wsum[lane] = x;
    }
    __syncthreads();
    int incl = val + (w > 0 ? wsum[w - 1] : 0);
    if (i < NSEG) g_soff[i + 1] = incl;
    if (t == 0) g_bsum[b] = wsum[31];
}
__global__ void scan2_kernel(int nb) {
    __shared__ int wsum[32];
    int t = threadIdx.x, lane = t & 31, w = t >> 5;
    int v = (t < nb) ? g_bsum[t] : 0;
    int val = v;
#pragma unroll
    for (int d = 1; d < 32; d <<= 1) {
        int u = __shfl_up_sync(0xFFFFFFFF, val, d);
        if (lane >= d) val += u;
    }
    if (lane == 31) wsum[w] = val;
    __syncthreads();
    if (w == 0) {
        int x = wsum[lane];
#pragma unroll
        for (int d = 1; d < 32; d <<= 1) {
            int u = __shfl_up_sync(0xFFFFFFFF, x, d);
            if (lane >= d) x += u;
        }
        wsum[lane] = x;
    }
    __syncthreads();
    int incl = val + (w > 0 ? wsum[w - 1] : 0);
    if (t < nb) g_boff[t] = incl - v;   // exclusive
}
__global__ void scan3_kernel() {
    int i = blockIdx.x * blockDim.x + threadIdx.x;
    if (i == 0) g_soff[0] = 0;
    if (i >= NSEG) return;
    int off = g_soff[i + 1] + g_boff[i >> 10];
    g_soff[i + 1] = off;
    g_cur2[i] = off - g_cnt2[i];
}

__global__ void scatter_kernel(const int* __restrict__ ei, const int* __restrict__ et) {
    int idx = blockIdx.x * blockDim.x + threadIdx.x;
    if (idx >= E2) return;
    int dest, src, s;
    if (idx < N_EDGES) { dest = ei[idx]; src = ei[N_EDGES + idx]; s = et[idx]; }
    else { int e = idx - N_EDGES; dest = ei[N_EDGES + e]; src = ei[e]; s = et[e] + R_REL; }
    int pos = atomicAdd(&g_cur2[dest * S_REL + s], 1);
    g_rec[pos] = src;
}

// -------- weight quantization (R8-exact) --------
__global__ void __launch_bounds__(128) convw_kernel(const float* __restrict__ w,
                                                    const float* __restrict__ b) {
    __shared__ float red[128];
    int lj = blockIdx.x;              // 0..255
    int l = lj >> 7, j = lj & 127;
    int t = threadIdx.x;

    float vals[20];
    float m = 0.f;
#pragma unroll
    for (int p = 0; p < 20; p++) {
        int k = t * 20 + p;
        float v = 0.f;
        if (k < 2432) {
            int s = k >> 7, kk = k & 127;
            v = w[(((size_t)l * NW + s) * EMB + kk) * EMB + j];
        } else if (k < 2432 + NW) {
            v = b[((size_t)l * NW + (k - 2432)) * EMB + j];
        }
        vals[p] = v;
        m = fmaxf(m, fabsf(v));
    }
    red[t] = m;
    __syncthreads();
    for (int d = 64; d > 0; d >>= 1) {
        if (t < d) red[t] = fmaxf(red[t], red[t + d]);
        __syncthreads();
    }
    float sb = fmaxf(red[0], 1e-30f);
    if (t == 0) g_sb[l * EMB + j] = sb;
    float inv = 1.f / sb;

    size_t rbase = (size_t)(l * EMB + j) * KW + (size_t)t * 5;   // 20 vals = 5 words
#pragma unroll
    for (int wq = 0; wq < 5; wq++) {
        int qh[4], ql[4];
#pragma unroll
        for (int c = 0; c < 4; c++) quant2(vals[wq * 4 + c], inv, qh[c], ql[c]);
        g_Pbhi[rbase + wq] = pack4(qh[0], qh[1], qh[2], qh[3]);
        g_Pblo[rbase + wq] = pack4(ql[0], ql[1], ql[2], ql[3]);
    }
}

// ---------------- aggregation + row quantization (block-per-node) ----------------
// R8 structure; NEW: max computed in registers at write time (no strided LDS max
// pass), fast quantizer with PRMT packing.
__global__ void __launch_bounds__(256) agg_kernel(const float* __restrict__ X) {
    __shared__ float row[KTOT];
    __shared__ float red[8];
    int i = blockIdx.x;
    int tid = threadIdx.x, lane = tid & 31, w = tid >> 5;
    int fo = lane << 2;

    float wmax = 0.f;
#pragma unroll
    for (int t = 0; t < 3; t++) {
        int slot = w + 8 * t;
        if (slot < S_REL) {
            int sb = i * S_REL + slot;
            int e0 = g_soff[sb], e1 = g_soff[sb + 1];
            float al = g_alpha2[sb];
            float4 a = make_float4(0.f, 0.f, 0.f, 0.f);
            for (int e = e0; e < e1; e++) {
                int src = g_rec[e];
                float4 v = *(const float4*)(X + (size_t)src * EMB + fo);
                a.x += v.x; a.y += v.y; a.z += v.z; a.w += v.w;
            }
            float fx = al * a.x, fy = al * a.y, fz = al * a.z, fw = al * a.w;
            row[slot * 128 + fo + 0] = fx;
            row[slot * 128 + fo + 1] = fy;
            row[slot * 128 + fo + 2] = fz;
            row[slot * 128 + fo + 3] = fw;
            wmax = fmaxf(wmax, fmaxf(fmaxf(fabsf(fx), fabsf(fy)),
                                     fmaxf(fabsf(fz), fabsf(fw))));
        } else if (slot == S_REL) {         // self slot
            float Ai = g_A[i];
            float4 v = *(const float4*)(X + (size_t)i * EMB + fo);
            float fx = Ai * v.x, fy = Ai * v.y, fz = Ai * v.z, fw = Ai * v.w;
            row[S_REL * 128 + fo + 0] = fx;
            row[S_REL * 128 + fo + 1] = fy;
            row[S_REL * 128 + fo + 2] = fz;
            row[S_REL * 128 + fo + 3] = fw;
            wmax = fmaxf(wmax, fmaxf(fmaxf(fabsf(fx), fabsf(fy)),
                                     fmaxf(fabsf(fz), fabsf(fw))));
        } else if (slot == NW) {            // bias block cols 2432..2559
#pragma unroll
            for (int c = 0; c < 4; c++) {
                int q = fo + c;
                float v = 0.f;
                if (q < S_REL)       v = g_gamma2[i * S_REL + q];
                else if (q == S_REL) v = g_A[i];
                row[2432 + q] = v;
                wmax = fmaxf(wmax, fabsf(v));
            }
        }
    }
    // warp-level max, then block max over 8 warps
#pragma unroll
    for (int d = 16; d > 0; d >>= 1) wmax = fmaxf(wmax, __shfl_xor_sync(0xFFFFFFFF, wmax, d));
    if (lane == 0) red[w] = wmax;
    __syncthreads();
    float gm = red[0];
#pragma unroll
    for (int q = 1; q < 8; q++) gm = fmaxf(gm, red[q]);
    float sa = fmaxf(gm, 1e-30f);
    if (tid == 0) g_sa[i] = sa;
    float inv = 1.f / sa;

    // quantize: KW = 640 words with 256 threads (R8 access pattern, fast quant)
    size_t rbase = (size_t)i * KW;
    for (int wq = tid; wq < KW; wq += 256) {
        const float* v4 = row + wq * 4;
        int qh[4], ql[4];
#pragma unroll
        for (int c = 0; c < 4; c++) quant_fast(v4[c], inv, qh[c], ql[c]);
        g_Qhi[rbase + wq] = prmt_pack(qh[0], qh[1], qh[2], qh[3]);
        g_Qlo[rbase + wq] = prmt_pack(ql[0], ql[1], ql[2], ql[3]);
    }
}

// --------------------------- int8 streaming GEMM (R8-exact) ---------------------------
__device__ __forceinline__ void fill_stage(uint32_t sbase, int k0, int m0, int tid,
                                           const char* __restrict__ Bh,
                                           const char* __restrict__ Bl) {
    const char* Ah = (const char*)g_Qhi;
    const char* Al = (const char*)g_Qlo;
#pragma unroll
    for (int p = 0; p < 4; p++) {
        int idx = tid + p * 256;          // 0..1023
        int rrow = idx >> 3, c = idx & 7; // 8 x 16B per 128B row
        uint32_t d = (uint32_t)(rrow * SROW2 + c * 16);
        size_t asrc = (size_t)(m0 + rrow) * KTOT + k0 + c * 16;
        cp_async16(sbase + OFF_AHI + d, Ah + asrc);
        cp_async16(sbase + OFF_ALO + d, Al + asrc);
        size_t bsrc = (size_t)rrow * KTOT + k0 + c * 16;
        cp_async16(sbase + OFF_BHI + d, Bh + bsrc);
        cp_async16(sbase + OFF_BLO + d, Bl + bsrc);
    }
}

__global__ void __launch_bounds__(256) gemm8_kernel(float* __restrict__ Out,
                                                    int layer, int do_relu) {
    extern __shared__ char dsm[];
    uint32_t sb = smem_u32(dsm);
    int tid = threadIdx.x, wid = tid >> 5, lane = tid & 31;
    int warp_m = wid & 1;
    int warp_n = wid >> 1;

    const char* Bh = (const char*)g_Pbhi + (size_t)layer * EMB * KTOT;
    const char* Bl = (const char*)g_Pblo + (size_t)layer * EMB * KTOT;

    uint32_t a_off = (uint32_t)((warp_m * 64 + (lane & 15)) * SROW2 + (lane >> 4) * 16);
    int bm = lane >> 3;
    uint32_t b_row = (uint32_t)(warp_n * 32 + ((bm >> 1) << 3) + (lane & 7));
    uint32_t b_koff = (uint32_t)((bm & 1) * 16);

    int m0 = blockIdx.x * 128;

    int acc1[4][4][4], acc2[4][4][4];
#pragma unroll
    for (int mi = 0; mi < 4; mi++)
#pragma unroll
        for (int ni = 0; ni < 4; ni++)
#pragma unroll
            for (int q = 0; q < 4; q++) { acc1[mi][ni][q] = 0; acc2[mi][ni][q] = 0; }

    fill_stage(sb, 0, m0, tid, Bh, Bl);
    CP_COMMIT();

    for (int u = 0; u < NCH; u++) {
        if (u + 1 < NCH) {
            fill_stage(sb + ((u + 1) & 1) * STAGE_SZ, (u + 1) * 128, m0, tid, Bh, Bl);
            CP_COMMIT();
            CP_WAIT1();
        } else {
            CP_WAIT0();
        }
        __syncthreads();

        uint32_t st = sb + (u & 1) * STAGE_SZ;
#pragma unroll
        for (int ks = 0; ks < 4; ks++) {            // k = 32 int8 per step
            uint32_t k2 = (uint32_t)(ks * 32);
            uint32_t Ah4[4][4], Al4[4][4];
#pragma unroll
            for (int mi = 0; mi < 4; mi++) {
                uint32_t ad = st + OFF_AHI + a_off + (uint32_t)(mi * 16 * SROW2) + k2;
                ldsm_x4(Ah4[mi], ad);
                ldsm_x4(Al4[mi], ad + (OFF_ALO - OFF_AHI));
            }
            uint32_t Bh4[4][2], Bl4[4][2];
#pragma unroll
            for (int nj = 0; nj < 2; nj++) {
                uint32_t bd = st + OFF_BHI + (b_row + nj * 16) * SROW2 + b_koff + k2;
                uint32_t r4[4];
                ldsm_x4(r4, bd);
                Bh4[nj * 2][0] = r4[0]; Bh4[nj * 2][1] = r4[1];
                Bh4[nj * 2 + 1][0] = r4[2]; Bh4[nj * 2 + 1][1] = r4[3];
                ldsm_x4(r4, bd + (OFF_BLO - OFF_BHI));
                Bl4[nj * 2][0] = r4[0]; Bl4[nj * 2][1] = r4[1];
                Bl4[nj * 2 + 1][0] = r4[2]; Bl4[nj * 2 + 1][1] = r4[3];
            }
#pragma unroll
            for (int mi = 0; mi < 4; mi++)
#pragma unroll
                for (int ni = 0; ni < 4; ni++) {
                    mma_s8(acc1[mi][ni], Ah4[mi], Bh4[ni]);
                    mma_s8(acc2[mi][ni], Ah4[mi], Bl4[ni]);
                    mma_s8(acc2[mi][ni], Al4[mi], Bh4[ni]);
                }
        }
        __syncthreads();
    }

    // epilogue: dequant + write
    int rbase = m0 + warp_m * 64 + (lane >> 2);
    int cbase = warp_n * 32 + (lane & 3) * 2;
    const float* sbp = g_sb + layer * EMB;
#pragma unroll
    for (int mi = 0; mi < 4; mi++) {
        int r = rbase + mi * 16;
#pragma unroll
        for (int ni = 0; ni < 4; ni++) {
            int c = cbase + ni * 8;
            float sb0 = sbp[c], sb1 = sbp[c + 1];
            if (r < N_NODES) {
                float sar = g_sa[r];
                float vx = sar * sb0 * ((float)acc1[mi][ni][0] * S1 + (float)acc2[mi][ni][0] * S2);
                float vy = sar * sb1 * ((float)acc1[mi][ni][1] * S1 + (float)acc2[mi][ni][1] * S2);
                if (do_relu) { vx = fmaxf(vx, 0.f); vy = fmaxf(vy, 0.f); }
                *(float2*)(Out + (size_t)r * EMB + c) = make_float2(vx, vy);
            }
            if (r + 8 < N_NODES) {
                float sar = g_sa[r + 8];
                float vx = sar * sb0 * ((float)acc1[mi][ni][2] * S1 + (float)acc2[mi][ni][2] * S2);
                float vy = sar * sb1 * ((float)acc1[mi][ni][3] * S1 + (float)acc2[mi][ni][3] * S2);
                if (do_relu) { vx = fmaxf(vx, 0.f); vy = fmaxf(vy, 0.f); }
                *(float2*)(Out + (size_t)(r + 8) * EMB + c) = make_float2(vx, vy);
            }
        }
    }
}

// ------------------------------ launch (R8-exact) ---------------------------------
extern "C" void kernel_launch(void* const* d_in, const int* in_sizes, int n_in,
                              void* d_out, int out_size) {
    const int*   ei  = (const int*)d_in[0];     // [2, E]
    const int*   et  = (const int*)d_in[1];     // [E]
    const float* emb = (const float*)d_in[2];   // [N, 128]
    const float* w   = (const float*)d_in[3];   // [2, 19, 128, 128]
    const float* b   = (const float*)d_in[4];   // [2, 19, 128]
    float* out = (float*)d_out;

    float* hptr = nullptr;
    cudaGetSymbolAddress((void**)&hptr, g_H);

    cudaFuncSetAttribute(gemm8_kernel,
                         cudaFuncAttributeMaxDynamicSharedMemorySize, GEMM_DSM);

    zero_kernel<<<512, 256>>>();
    hist_kernel<<<(E2 + 255) / 256, 256>>>(ei, et);
    alpha_kernel<<<(N_NODES + 255) / 256, 256>>>();
    int nb = (NSEG + 1023) / 1024;   // 879
    scan1_kernel<<<nb, 1024>>>();
    scan2_kernel<<<1, 1024>>>(nb);
    scan3_kernel<<<(NSEG + 255) / 256, 256>>>();
    scatter_kernel<<<(E2 + 255) / 256, 256>>>(ei, et);
    convw_kernel<<<2 * EMB, 128>>>(w, b);

    // layer 0: emb -> H (relu)
    agg_kernel<<<N_NODES, 256>>>(emb);
    gemm8_kernel<<<TILES_M, 256, GEMM_DSM>>>(hptr, 0, 1);
    // layer 1: H -> out
    agg_kernel<<<N_NODES, 256>>>(hptr);
    gemm8_kernel<<<TILES_M, 256, GEMM_DSM>>>(out, 1, 0);
}

// round 13
// speedup vs baseline: 1.1333x; 1.0321x over previous
#include <cuda_runtime.h>
#include <cuda_bf16.h>
#include <cstdint>

#define N_NODES 50000
#define NPAD    50048             // 391*128
#define EMB     128
#define R_REL   9
#define S_REL   18
#define NW      19
#define N_EDGES 800000
#define E2      (2*N_EDGES)
#define NSEG    (S_REL*N_NODES)   // 900000
#define KTOT    2560              // 20 slots x 128 cols
#define KW      640               // KTOT/4 packed words per row
#define NCH     20                // K chunks of 128
#define TILES_M 391

// smem: 4 int8 arrays (Ahi,Alo,Bhi,Blo) x 2 stages; 128 rows x 128 s8, stride 144
#define SROW2   144
#define ATILE2  18432             // 128*144
#define STAGE_SZ (4*ATILE2)       // 73728
#define OFF_AHI 0
#define OFF_ALO ATILE2
#define OFF_BHI (2*ATILE2)
#define OFF_BLO (3*ATILE2)
#define GEMM_DSM (2*STAGE_SZ)     // 147456

#define S1 6.103515625e-5f        // 2^-14
#define S2 4.76837158203125e-7f   // 2^-21

// -------- scratch (device globals) --------
__device__ int   g_cnt2[NSEG];
__device__ float g_alpha2[NSEG];
__device__ float g_gamma2[NSEG];
__device__ float g_A[N_NODES];
__device__ int   g_soff[NSEG + 1];
__device__ int   g_cur2[NSEG];
__device__ int   g_bsum[1024];
__device__ int   g_boff[1024];
__device__ int   g_rec[E2];
__device__ float g_H[(size_t)N_NODES * EMB];
__device__ unsigned int g_Qhi[(size_t)NPAD * KW];    // ~128 MB
__device__ unsigned int g_Qlo[(size_t)NPAD * KW];    // ~128 MB
__device__ unsigned int g_Pbhi[2 * EMB * KW];
__device__ unsigned int g_Pblo[2 * EMB * KW];
__device__ float g_sa[N_NODES];
__device__ float g_sb[2 * EMB];

// ------------------------- PTX helpers -------------------------
__device__ __forceinline__ uint32_t smem_u32(const void* p) {
    uint32_t a;
    asm("{ .reg .u64 t; cvta.to.shared.u64 t, %1; cvt.u32.u64 %0, t; }" : "=r"(a) : "l"(p));
    return a;
}
__device__ __forceinline__ void cp_async16(uint32_t dst, const void* src) {
    asm volatile("cp.async.cg.shared.global [%0], [%1], 16;"
                 :: "r"(dst), "l"(src) : "memory");
}
#define CP_COMMIT() asm volatile("cp.async.commit_group;" ::: "memory")
#define CP_WAIT1()  asm volatile("cp.async.wait_group 1;" ::: "memory")
#define CP_WAIT0()  asm volatile("cp.async.wait_group 0;" ::: "memory")

__device__ __forceinline__ void ldsm_x4(uint32_t* r, uint32_t addr) {
    asm volatile("ldmatrix.sync.aligned.m8n8.x4.shared.b16 {%0,%1,%2,%3}, [%4];"
                 : "=r"(r[0]), "=r"(r[1]), "=r"(r[2]), "=r"(r[3]) : "r"(addr));
}
__device__ __forceinline__ void mma_s8(int* c, const uint32_t* a, const uint32_t* b) {
    asm volatile("mma.sync.aligned.m16n8k32.row.col.s32.s8.s8.s32 "
                 "{%0,%1,%2,%3}, {%4,%5,%6,%7}, {%8,%9}, {%0,%1,%2,%3};"
                 : "+r"(c[0]), "+r"(c[1]), "+r"(c[2]), "+r"(c[3])
                 : "r"(a[0]), "r"(a[1]), "r"(a[2]), "r"(a[3]), "r"(b[0]), "r"(b[1]));
}

// convw-side quantizer — unchanged
__device__ __forceinline__ void quant2(float v, float inv_sa, int& qh, int& ql) {
    float u = v * inv_sa;
    float qhf = rintf(u * 128.f);
    qhf = fminf(fmaxf(qhf, -127.f), 127.f);
    float r1 = u - qhf * 0.0078125f;            // 1/128
    float qlf = rintf(r1 * 16384.f);
    qlf = fminf(fmaxf(qlf, -127.f), 127.f);
    qh = (int)qhf;
    ql = (int)qlf;
}
__device__ __forceinline__ unsigned int pack4(int a, int b, int c, int d) {
    return (unsigned int)(a & 0xff) | ((unsigned int)(b & 0xff) << 8)
         | ((unsigned int)(c & 0xff) << 16) | ((unsigned int)(d & 0xff) << 24);
}

// fast agg-side quantizer + PRMT packing
__device__ __forceinline__ unsigned int prmt_pack(int a, int b, int c, int d) {
    unsigned int p01 = __byte_perm((unsigned int)a, (unsigned int)b, 0x0040);
    unsigned int p23 = __byte_perm((unsigned int)c, (unsigned int)d, 0x0040);
    return __byte_perm(p01, p23, 0x5410);
}
__device__ __forceinline__ void quant_fast(float v, float inv_sa, int& qh, int& ql) {
    float u = v * inv_sa;                         // |u| <= 1
    float s = fminf(fmaxf(u * 128.f, -127.f), 127.f);
    float qhf = rintf(s);
    qh = (int)qhf;
    float r1 = fmaf(qhf, -0.0078125f, u);
    ql = min(__float2int_rn(r1 * 16384.f), 127);  // low clamp unneeded (-128 fits s8)
}

// ---------------------------- preprocessing (R8-exact) ----------------------------
__global__ void zero_kernel() {
    for (int idx = blockIdx.x * blockDim.x + threadIdx.x; idx < NSEG;
         idx += gridDim.x * blockDim.x) g_cnt2[idx] = 0;
}

__global__ void hist_kernel(const int* __restrict__ ei, const int* __restrict__ et) {
    int idx = blockIdx.x * blockDim.x + threadIdx.x;
    if (idx >= E2) return;
    int dest, s;
    if (idx < N_EDGES) { dest = ei[idx]; s = et[idx]; }
    else { int e = idx - N_EDGES; dest = ei[N_EDGES + e]; s = et[e] + R_REL; }
    atomicAdd(&g_cnt2[dest * S_REL + s], 1);
}

__global__ void alpha_kernel() {
    int i = blockIdx.x * blockDim.x + threadIdx.x;
    if (i >= N_NODES) return;
    int cnt[S_REL];
#pragma unroll
    for (int s = 0; s < S_REL; s++) cnt[s] = g_cnt2[i * S_REL + s];
    float suffix = 1.0f;
#pragma unroll
    for (int k = S_REL - 1; k >= 0; k--) {
        int s = (k >> 1) + R_REL * (k & 1);
        int c = cnt[s];
        float f = 2.0f / (float)(c > 0 ? c : 1);
        suffix *= f;
        g_alpha2[i * S_REL + s] = suffix;
        g_gamma2[i * S_REL + s] = suffix * (float)c;
    }
    g_A[i] = suffix;
}

__global__ void scan1_kernel() {
    __shared__ int wsum[32];
    int b = blockIdx.x, t = threadIdx.x;
    int i = b * 1024 + t;
    int lane = t & 31, w = t >> 5;
    int v = (i < NSEG) ? g_cnt2[i] : 0;
    int val = v;
#pragma unroll
    for (int d = 1; d < 32; d <<= 1) {
        int u = __shfl_up_sync(0xFFFFFFFF, val, d);
        if (lane >= d) val += u;
    }
    if (lane == 31) wsum[w] = val;
    __syncthreads();
    if (w == 0) {
        int x = wsum[lane];
#pragma unroll
        for (int d = 1; d < 32; d <<= 1) {
            int u = __shfl_up_sync(0xFFFFFFFF, x, d);
            if (lane >= d) x += u;
        }
        wsum[lane] = x;
    }
    __syncthreads();
    int incl = val + (w > 0 ? wsum[w - 1] : 0);
    if (i < NSEG) g_soff[i + 1] = incl;
    if (t == 0) g_bsum[b] = wsum[31];
}
__global__ void scan2_kernel(int nb) {
    __shared__ int wsum[32];
    int t = threadIdx.x, lane = t & 31, w = t >> 5;
    int v = (t < nb) ? g_bsum[t] : 0;
    int val = v;
#pragma unroll
    for (int d = 1; d < 32; d <<= 1) {
        int u = __shfl_up_sync(0xFFFFFFFF, val, d);
        if (lane >= d) val += u;
    }
    if (lane == 31) wsum[w] = val;
    __syncthreads();
    if (w == 0) {
        int x = wsum[lane];
#pragma unroll
        for (int d = 1; d < 32; d <<= 1) {
            int u = __shfl_up_sync(0xFFFFFFFF, x, d);
            if (lane >= d) x += u;
        }
        wsum[lane] = x;
    }
    __syncthreads();
    int incl = val + (w > 0 ? wsum[w - 1] : 0);
    if (t < nb) g_boff[t] = incl - v;   // exclusive
}
__global__ void scan3_kernel() {
    int i = blockIdx.x * blockDim.x + threadIdx.x;
    if (i == 0) g_soff[0] = 0;
    if (i >= NSEG) return;
    int off = g_soff[i + 1] + g_boff[i >> 10];
    g_soff[i + 1] = off;
    g_cur2[i] = off - g_cnt2[i];
}

__global__ void scatter_kernel(const int* __restrict__ ei, const int* __restrict__ et) {
    int idx = blockIdx.x * blockDim.x + threadIdx.x;
    if (idx >= E2) return;
    int dest, src, s;
    if (idx < N_EDGES) { dest = ei[idx]; src = ei[N_EDGES + idx]; s = et[idx]; }
    else { int e = idx - N_EDGES; dest = ei[N_EDGES + e]; src = ei[e]; s = et[e] + R_REL; }
    int pos = atomicAdd(&g_cur2[dest * S_REL + s], 1);
    g_rec[pos] = src;
}

// -------- weight quantization (R8-exact) --------
__global__ void __launch_bounds__(128) convw_kernel(const float* __restrict__ w,
                                                    const float* __restrict__ b) {
    __shared__ float red[128];
    int lj = blockIdx.x;              // 0..255
    int l = lj >> 7, j = lj & 127;
    int t = threadIdx.x;

    float vals[20];
    float m = 0.f;
#pragma unroll
    for (int p = 0; p < 20; p++) {
        int k = t * 20 + p;
        float v = 0.f;
        if (k < 2432) {
            int s = k >> 7, kk = k & 127;
            v = w[(((size_t)l * NW + s) * EMB + kk) * EMB + j];
        } else if (k < 2432 + NW) {
            v = b[((size_t)l * NW + (k - 2432)) * EMB + j];
        }
        vals[p] = v;
        m = fmaxf(m, fabsf(v));
    }
    red[t] = m;
    __syncthreads();
    for (int d = 64; d > 0; d >>= 1) {
        if (t < d) red[t] = fmaxf(red[t], red[t + d]);
        __syncthreads();
    }
    float sb = fmaxf(red[0], 1e-30f);
    if (t == 0) g_sb[l * EMB + j] = sb;
    float inv = 1.f / sb;

    size_t rbase = (size_t)(l * EMB + j) * KW + (size_t)t * 5;   // 20 vals = 5 words
#pragma unroll
    for (int wq = 0; wq < 5; wq++) {
        int qh[4], ql[4];
#pragma unroll
        for (int c = 0; c < 4; c++) quant2(vals[wq * 4 + c], inv, qh[c], ql[c]);
        g_Pbhi[rbase + wq] = pack4(qh[0], qh[1], qh[2], qh[3]);
        g_Pblo[rbase + wq] = pack4(ql[0], ql[1], ql[2], ql[3]);
    }
}

// ---------------- aggregation + quantization: fully register-resident ----------------
// 256 threads per node; warp w owns slots {w, w+8, w+16}; lane owns cols fo..fo+3.
// Values never touch smem: gather -> v[t][4] regs -> block max -> quantize -> STG.
__global__ void __launch_bounds__(256) agg_kernel(const float* __restrict__ X) {
    __shared__ float red[8];
    int i = blockIdx.x;
    int tid = threadIdx.x, lane = tid & 31, w = tid >> 5;
    int fo = lane << 2;

    float v[3][4];
#pragma unroll
    for (int t = 0; t < 3; t++)
#pragma unroll
        for (int c = 0; c < 4; c++) v[t][c] = 0.f;

    float wmax = 0.f;
#pragma unroll
    for (int t = 0; t < 3; t++) {
        int slot = w + 8 * t;
        if (slot < S_REL) {
            int sb = i * S_REL + slot;
            int e0 = g_soff[sb], e1 = g_soff[sb + 1];
            float al = g_alpha2[sb];
            float4 a = make_float4(0.f, 0.f, 0.f, 0.f);
            for (int e = e0; e < e1; e++) {
                int src = g_rec[e];
                float4 x4 = *(const float4*)(X + (size_t)src * EMB + fo);
                a.x += x4.x; a.y += x4.y; a.z += x4.z; a.w += x4.w;
            }
            v[t][0] = al * a.x; v[t][1] = al * a.y;
            v[t][2] = al * a.z; v[t][3] = al * a.w;
        } else if (slot == S_REL) {         // self slot
            float Ai = g_A[i];
            float4 x4 = *(const float4*)(X + (size_t)i * EMB + fo);
            v[t][0] = Ai * x4.x; v[t][1] = Ai * x4.y;
            v[t][2] = Ai * x4.z; v[t][3] = Ai * x4.w;
        } else if (slot == NW) {            // bias block cols 2432..2559
#pragma unroll
            for (int c = 0; c < 4; c++) {
                int q = fo + c;
                float bv = 0.f;
                if (q < S_REL)       bv = g_gamma2[i * S_REL + q];
                else if (q == S_REL) bv = g_A[i];
                v[t][c] = bv;
            }
        }
#pragma unroll
        for (int c = 0; c < 4; c++) wmax = fmaxf(wmax, fabsf(v[t][c]));
    }

    // warp max -> block max over 8 warps
#pragma unroll
    for (int d = 16; d > 0; d >>= 1) wmax = fmaxf(wmax, __shfl_xor_sync(0xFFFFFFFF, wmax, d));
    if (lane == 0) red[w] = wmax;
    __syncthreads();
    float gm = red[0];
#pragma unroll
    for (int q = 1; q < 8; q++) gm = fmaxf(gm, red[q]);
    float sa = fmaxf(gm, 1e-30f);
    if (tid == 0) g_sa[i] = sa;
    float inv = 1.f / sa;

    // quantize straight from registers; coalesced 32-bit stores
    size_t rbase = (size_t)i * KW;
#pragma unroll
    for (int t = 0; t < 3; t++) {
        int slot = w + 8 * t;
        if (slot < 20) {
            int qh[4], ql[4];
#pragma unroll
            for (int c = 0; c < 4; c++) quant_fast(v[t][c], inv, qh[c], ql[c]);
            size_t widx = rbase + slot * 32 + lane;
            g_Qhi[widx] = prmt_pack(qh[0], qh[1], qh[2], qh[3]);
            g_Qlo[widx] = prmt_pack(ql[0], ql[1], ql[2], ql[3]);
        }
    }
}

// --------------------------- int8 streaming GEMM (R8-exact) ---------------------------
__device__ __forceinline__ void fill_stage(uint32_t sbase, int k0, int m0, int tid,
                                           const char* __restrict__ Bh,
                                           const char* __restrict__ Bl) {
    const char* Ah = (const char*)g_Qhi;
    const char* Al = (const char*)g_Qlo;
#pragma unroll
    for (int p = 0; p < 4; p++) {
        int idx = tid + p * 256;          // 0..1023
        int rrow = idx >> 3, c = idx & 7; // 8 x 16B per 128B row
        uint32_t d = (uint32_t)(rrow * SROW2 + c * 16);
        size_t asrc = (size_t)(m0 + rrow) * KTOT + k0 + c * 16;
        cp_async16(sbase + OFF_AHI + d, Ah + asrc);
        cp_async16(sbase + OFF_ALO + d, Al + asrc);
        size_t bsrc = (size_t)rrow * KTOT + k0 + c * 16;
        cp_async16(sbase + OFF_BHI + d, Bh + bsrc);
        cp_async16(sbase + OFF_BLO + d, Bl + bsrc);
    }
}

__global__ void __launch_bounds__(256) gemm8_kernel(float* __restrict__ Out,
                                                    int layer, int do_relu) {
    extern __shared__ char dsm[];
    uint32_t sb = smem_u32(dsm);
    int tid = threadIdx.x, wid = tid >> 5, lane = tid & 31;
    int warp_m = wid & 1;
    int warp_n = wid >> 1;

    const char* Bh = (const char*)g_Pbhi + (size_t)layer * EMB * KTOT;
    const char* Bl = (const char*)g_Pblo + (size_t)layer * EMB * KTOT;

    uint32_t a_off = (uint32_t)((warp_m * 64 + (lane & 15)) * SROW2 + (lane >> 4) * 16);
    int bm = lane >> 3;
    uint32_t b_row = (uint32_t)(warp_n * 32 + ((bm >> 1) << 3) + (lane & 7));
    uint32_t b_koff = (uint32_t)((bm & 1) * 16);

    int m0 = blockIdx.x * 128;

    int acc1[4][4][4], acc2[4][4][4];
#pragma unroll
    for (int mi = 0; mi < 4; mi++)
#pragma unroll
        for (int ni = 0; ni < 4; ni++)
#pragma unroll
            for (int q = 0; q < 4; q++) { acc1[mi][ni][q] = 0; acc2[mi][ni][q] = 0; }

    fill_stage(sb, 0, m0, tid, Bh, Bl);
    CP_COMMIT();

    for (int u = 0; u < NCH; u++) {
        if (u + 1 < NCH) {
            fill_stage(sb + ((u + 1) & 1) * STAGE_SZ, (u + 1) * 128, m0, tid, Bh, Bl);
            CP_COMMIT();
            CP_WAIT1();
        } else {
            CP_WAIT0();
        }
        __syncthreads();

        uint32_t st = sb + (u & 1) * STAGE_SZ;
#pragma unroll
        for (int ks = 0; ks < 4; ks++) {            // k = 32 int8 per step
            uint32_t k2 = (uint32_t)(ks * 32);
            uint32_t Ah4[4][4], Al4[4][4];
#pragma unroll
            for (int mi = 0; mi < 4; mi++) {
                uint32_t ad = st + OFF_AHI + a_off + (uint32_t)(mi * 16 * SROW2) + k2;
                ldsm_x4(Ah4[mi], ad);
                ldsm_x4(Al4[mi], ad + (OFF_ALO - OFF_AHI));
            }
            uint32_t Bh4[4][2], Bl4[4][2];
#pragma unroll
            for (int nj = 0; nj < 2; nj++) {
                uint32_t bd = st + OFF_BHI + (b_row + nj * 16) * SROW2 + b_koff + k2;
                uint32_t r4[4];
                ldsm_x4(r4, bd);
                Bh4[nj * 2][0] = r4[0]; Bh4[nj * 2][1] = r4[1];
                Bh4[nj * 2 + 1][0] = r4[2]; Bh4[nj * 2 + 1][1] = r4[3];
                ldsm_x4(r4, bd + (OFF_BLO - OFF_BHI));
                Bl4[nj * 2][0] = r4[0]; Bl4[nj * 2][1] = r4[1];
                Bl4[nj * 2 + 1][0] = r4[2]; Bl4[nj * 2 + 1][1] = r4[3];
            }
#pragma unroll
            for (int mi = 0; mi < 4; mi++)
#pragma unroll
                for (int ni = 0; ni < 4; ni++) {
                    mma_s8(acc1[mi][ni], Ah4[mi], Bh4[ni]);
                    mma_s8(acc2[mi][ni], Ah4[mi], Bl4[ni]);
                    mma_s8(acc2[mi][ni], Al4[mi], Bh4[ni]);
                }
        }
        __syncthreads();
    }

    // epilogue: dequant + write
    int rbase = m0 + warp_m * 64 + (lane >> 2);
    int cbase = warp_n * 32 + (lane & 3) * 2;
    const float* sbp = g_sb + layer * EMB;
#pragma unroll
    for (int mi = 0; mi < 4; mi++) {
        int r = rbase + mi * 16;
#pragma unroll
        for (int ni = 0; ni < 4; ni++) {
            int c = cbase + ni * 8;
            float sb0 = sbp[c], sb1 = sbp[c + 1];
            if (r < N_NODES) {
                float sar = g_sa[r];
                float vx = sar * sb0 * ((float)acc1[mi][ni][0] * S1 + (float)acc2[mi][ni][0] * S2);
                float vy = sar * sb1 * ((float)acc1[mi][ni][1] * S1 + (float)acc2[mi][ni][1] * S2);
                if (do_relu) { vx = fmaxf(vx, 0.f); vy = fmaxf(vy, 0.f); }
                *(float2*)(Out + (size_t)r * EMB + c) = make_float2(vx, vy);
            }
            if (r + 8 < N_NODES) {
                float sar = g_sa[r + 8];
                float vx = sar * sb0 * ((float)acc1[mi][ni][2] * S1 + (float)acc2[mi][ni][2] * S2);
                float vy = sar * sb1 * ((float)acc1[mi][ni][3] * S1 + (float)acc2[mi][ni][3] * S2);
                if (do_relu) { vx = fmaxf(vx, 0.f); vy = fmaxf(vy, 0.f); }
                *(float2*)(Out + (size_t)(r + 8) * EMB + c) = make_float2(vx, vy);
            }
        }
    }
}

// ------------------------------ launch (R8-exact) ---------------------------------
extern "C" void kernel_launch(void* const* d_in, const int* in_sizes, int n_in,
                              void* d_out, int out_size) {
    const int*   ei  = (const int*)d_in[0];     // [2, E]
    const int*   et  = (const int*)d_in[1];     // [E]
    const float* emb = (const float*)d_in[2];   // [N, 128]
    const float* w   = (const float*)d_in[3];   // [2, 19, 128, 128]
    const float* b   = (const float*)d_in[4];   // [2, 19, 128]
    float* out = (float*)d_out;

    float* hptr = nullptr;
    cudaGetSymbolAddress((void**)&hptr, g_H);

    cudaFuncSetAttribute(gemm8_kernel,
                         cudaFuncAttributeMaxDynamicSharedMemorySize, GEMM_DSM);

    zero_kernel<<<512, 256>>>();
    hist_kernel<<<(E2 + 255) / 256, 256>>>(ei, et);
    alpha_kernel<<<(N_NODES + 255) / 256, 256>>>();
    int nb = (NSEG + 1023) / 1024;   // 879
    scan1_kernel<<<nb, 1024>>>();
    scan2_kernel<<<1, 1024>>>(nb);
    scan3_kernel<<<(NSEG + 255) / 256, 256>>>();
    scatter_kernel<<<(E2 + 255) / 256, 256>>>(ei, et);
    convw_kernel<<<2 * EMB, 128>>>(w, b);

    // layer 0: emb -> H (relu)
    agg_kernel<<<N_NODES, 256>>>(emb);
    gemm8_kernel<<<TILES_M, 256, GEMM_DSM>>>(hptr, 0, 1);
    // layer 1: H -> out
    agg_kernel<<<N_NODES, 256>>>(hptr);
    gemm8_kernel<<<TILES_M, 256, GEMM_DSM>>>(out, 1, 0);
}